// round 6
// baseline (speedup 1.0000x reference)
#include <cuda_runtime.h>

// Problem shape (fixed by the dataset)
#define BB 256
#define SS 2048
#define HH 128
#define NB 2
#define NTHREADS 512
#define DT 0.1f
#define PAD 36           // floats per 32-float chunk (16B pad kills bank conflicts)
#define HPAD (4 * PAD)   // 144 floats per padded state vector

typedef unsigned long long ull;

// Packed fp32x2 FMA (Blackwell): two fp32 MACs per instruction.
__device__ __forceinline__ ull ffma2(ull a, ull b, ull c) {
    ull d;
    asm("fma.rn.f32x2 %0, %1, %2, %3;" : "=l"(d) : "l"(a), "l"(b), "l"(c));
    return d;
}
__device__ __forceinline__ float fold2(ull a) {
    float lo, hi;
    asm("mov.b64 {%0, %1}, %2;" : "=f"(lo), "=f"(hi) : "l"(a));
    return lo + hi;
}
__device__ __forceinline__ float tanha(float x) {
    float t; asm("tanh.approx.f32 %0, %1;" : "=f"(t) : "f"(x)); return t;
}

// 8-float dot partials for 4 butterfly-ordered rows, two matrices sharing the
// same vector chunk. v points at this lane's 8 floats (padded layout).
__device__ __forceinline__ void mv8x2(const ulonglong2 (&wk)[4][2],
                                      const ulonglong2 (&ws)[4][2],
                                      const float* v, float (&fk)[4], float (&fs)[4]) {
    const ulonglong2 v0 = *reinterpret_cast<const ulonglong2*>(v);
    const ulonglong2 v1 = *reinterpret_cast<const ulonglong2*>(v + 4);
#pragma unroll
    for (int j = 0; j < 4; j++) {
        ull a = ffma2(wk[j][0].x, v0.x, 0ULL);
        a = ffma2(wk[j][0].y, v0.y, a);
        a = ffma2(wk[j][1].x, v1.x, a);
        a = ffma2(wk[j][1].y, v1.y, a);
        fk[j] = fold2(a);
        ull b = ffma2(ws[j][0].x, v0.x, 0ULL);
        b = ffma2(ws[j][0].y, v0.y, b);
        b = ffma2(ws[j][1].x, v1.x, b);
        b = ffma2(ws[j][1].y, v1.y, b);
        fs[j] = fold2(b);
    }
}
// Single-matrix variant (phase B).
__device__ __forceinline__ void mv8x1(const ulonglong2 (&wr)[4][2],
                                      const float* v, float (&fr)[4]) {
    const ulonglong2 v0 = *reinterpret_cast<const ulonglong2*>(v);
    const ulonglong2 v1 = *reinterpret_cast<const ulonglong2*>(v + 4);
#pragma unroll
    for (int j = 0; j < 4; j++) {
        ull a = ffma2(wr[j][0].x, v0.x, 0ULL);
        a = ffma2(wr[j][0].y, v0.y, a);
        a = ffma2(wr[j][1].x, v1.x, a);
        a = ffma2(wr[j][1].y, v1.y, a);
        fr[j] = fold2(a);
    }
}
// Butterfly reduce over the 16-lane group, slots pre-permuted so no selects:
// partner's slot2/3 at xor8 (and slot1 at xor4) are exactly this lane's rows.
__device__ __forceinline__ void red84(float (&fk)[4], float (&fs)[4], float& K, float& S) {
    fk[0] += __shfl_xor_sync(0xffffffffu, fk[2], 8);
    fk[1] += __shfl_xor_sync(0xffffffffu, fk[3], 8);
    fs[0] += __shfl_xor_sync(0xffffffffu, fs[2], 8);
    fs[1] += __shfl_xor_sync(0xffffffffu, fs[3], 8);
    K = fk[0] + __shfl_xor_sync(0xffffffffu, fk[1], 4);
    S = fs[0] + __shfl_xor_sync(0xffffffffu, fs[1], 4);
}
__device__ __forceinline__ float red41(float (&fr)[4]) {
    fr[0] += __shfl_xor_sync(0xffffffffu, fr[2], 8);
    fr[1] += __shfl_xor_sync(0xffffffffu, fr[3], 8);
    return fr[0] + __shfl_xor_sync(0xffffffffu, fr[1], 4);
}

__global__ void __launch_bounds__(NTHREADS, 1)
liquid_scan_kernel(const float* __restrict__ x,
                   const float* __restrict__ W_in, const float* __restrict__ b_in,
                   const float* __restrict__ W_rec, const float* __restrict__ b_rec,
                   const float* __restrict__ tau,
                   const float* __restrict__ W_att, const float* __restrict__ b_att,
                   const float* __restrict__ W_ev, const float* __restrict__ b_ev,
                   const float* __restrict__ W_acc, const float* __restrict__ b_acc,
                   const float* __restrict__ W_out, const float* __restrict__ b_out,
                   float* __restrict__ out) {
    __shared__ __align__(16) float xs[NB][SS];       // input rows
    __shared__ __align__(16) float ews[NB][SS];      // event weights
    __shared__ __align__(16) float hs[NB][HPAD];     // hidden state (padded chunks)
    __shared__ __align__(16) float hatts[NB][HPAD];  // h * att (padded chunks)

    const int tid = threadIdx.x;
    const int G = tid >> 4;          // 16-lane group: rows 4G..4G+3
    const int L = tid & 15;          // lane within group
    const int r_own = L >> 2;        // row this lane owns after reduction
    const int q = tid & 3;           // lane role (same scheme as before)
    const int p = q & 1;             // batch parity for this lane's role
    const int bit0 = L & 1;          // batch-order bit (scattered at xor1)
    const int bit1 = (L >> 1) & 1;   // matrix-swap bit (scattered at xor2)
    const int h = 4 * G + r_own;     // owned row
    const int b0 = blockIdx.x * NB;
    const int vb = r_own * PAD + 8 * q;           // padded float offset of this lane's 8 cols
    const int hoff = (h >> 5) * PAD + (h & 31);   // padded scalar index for row h

    // ---- stage x rows into smem
    {
        const float4* xg0 = reinterpret_cast<const float4*>(x + (size_t)b0 * SS);
        const float4* xg1 = reinterpret_cast<const float4*>(x + (size_t)(b0 + 1) * SS);
        reinterpret_cast<float4*>(xs[0])[tid] = xg0[tid];
        reinterpret_cast<float4*>(xs[1])[tid] = xg1[tid];
    }
    if (tid < HPAD) { hs[0][tid] = 0.0f; hs[1][tid] = 0.0f; }
    __syncthreads();

    // ---- precompute event weights into smem AND the event_weights output
    {
        const float wev0 = W_ev[0], wev1 = W_ev[1], bev = b_ev[0];
        float* out_ew = out + BB;
#pragma unroll
        for (int k = 0; k < SS / NTHREADS; k++) {
            const int s = tid + k * NTHREADS;
#pragma unroll
            for (int b = 0; b < NB; b++) {
                float e = 0.0f;
                if (s > 0) {
                    float t = tanha(0.5f * (wev0 * xs[b][s] + wev1 * xs[b][s - 1] + bev));
                    e = fmaf(0.5f, t, 0.5f);
                }
                ews[b][s] = e;
                out_ew[(size_t)(b0 + b) * SS + s] = e;
            }
        }
    }

    // ---- weights into registers, butterfly-permuted:
    // slot j holds row 4G + (r_own ^ j); phase-A "kept" matrix per lane-bit1.
    const float* WmK = bit1 ? W_acc : W_att;
    const float* WmS = bit1 ? W_att : W_acc;
    ulonglong2 wk[4][2], wsn[4][2], wrr[4][2];
#pragma unroll
    for (int j = 0; j < 4; j++) {
        const int row = 4 * G + (r_own ^ j);
        const float* pk = WmK + row * HH + 8 * L;
        const float* ps = WmS + row * HH + 8 * L;
        const float* pr = W_rec + row * HH + 8 * L;
        wk[j][0] = reinterpret_cast<const ulonglong2*>(pk)[0];
        wk[j][1] = reinterpret_cast<const ulonglong2*>(pk + 4)[0];
        wsn[j][0] = reinterpret_cast<const ulonglong2*>(ps)[0];
        wsn[j][1] = reinterpret_cast<const ulonglong2*>(ps + 4)[0];
        wrr[j][0] = reinterpret_cast<const ulonglong2*>(pr)[0];
        wrr[j][1] = reinterpret_cast<const ulonglong2*>(pr + 4)[0];
    }

    const float pA_bias = (q < 2) ? b_att[h] : b_acc[h];
    const float brec = b_rec[h];
    const float win  = W_in[h];
    const float bin  = b_in[h];
    const float itau = 1.0f / fminf(fmaxf(tau[h], 0.1f), 10.0f);

    // Batch-order pointers (first = lane's kept batch, scattered at xor1).
    const float* hAf = &hs[bit0][vb];
    const float* hAs = &hs[bit0 ^ 1][vb];
    const float* hBf = &hatts[bit0][vb];
    const float* hBs = &hatts[bit0 ^ 1][vb];

    float accq = 0.0f;   // acc state: q2 = acc[b0], q3 = acc[b1]
    float ewpq = 0.0f;   // previous step's event weight (pipelined acc)

    __syncthreads();

#pragma unroll 1
    for (int s = 0; s < SS; s++) {
        // ---- phase A: att + acc matvecs on h_s (kept/sent matrices per lane)
        float fk[4], fs[4], Kf, Sf, Ks, Ss;
        mv8x2(wk, wsn, hAf, fk, fs);
        red84(fk, fs, Kf, Sf);
        mv8x2(wk, wsn, hAs, fk, fs);
        red84(fk, fs, Ks, Ss);
        Kf += __shfl_xor_sync(0xffffffffu, Sf, 2);  // partner's sent = my kept matrix
        Ks += __shfl_xor_sync(0xffffffffu, Ss, 2);
        Kf += __shfl_xor_sync(0xffffffffu, Ks, 1);  // partner's 2nd batch = my 1st
        // Kf = full dot for (row h, matrix by q-bit1, batch by q-bit0)
        const float inA = Kf + pA_bias;
        const float tA = tanha((q < 2) ? 0.5f * inA : inA);
        const float vA = (q < 2) ? fmaf(0.5f, tA, 0.5f) : tA;

        const float hold = hs[p][hoff];
        if (q < 2) hatts[p][hoff] = hold * vA;     // q0 -> b0, q1 -> b1
        accq = 0.9f * accq + 0.1f * vA * ewpq;     // meaningful on q2/q3
        __syncthreads();

        // ---- phase B: recurrence matvec on h*att, state update
        float fr[4];
        mv8x1(wrr, hBf, fr);
        float Rf = red41(fr);
        mv8x1(wrr, hBs, fr);
        float Rs = red41(fr);
        Rf += __shfl_xor_sync(0xffffffffu, Rf, 2);  // all-reduce over matrix bit
        Rs += __shfl_xor_sync(0xffffffffu, Rs, 2);
        Rf += __shfl_xor_sync(0xffffffffu, Rs, 1);  // batch scatter

        const float xq = xs[p][s];
        const float ewq = ews[p][s];
        // roles: q0->rec(b0), q1->rec(b1), q2->ic(b0), q3->ic(b1)
        const float inB = (q & 2) ? fmaf(win, xq, bin) : (Rf + brec);
        const float tB = tanha(inB);
        const float icx = __shfl_xor_sync(0xffffffffu, tB, 2);
        const float hn = hold + DT * ((icx + tB - hold) * itau) * (1.0f + ewq);
        if (q < 2) hs[p][hoff] = hn;
        ewpq = ewq;
        __syncthreads();
    }

    // ---- trailing acc update: tanh(W_acc @ h_S) with ew_{S-1}
    {
        float fk[4], fs[4], Kf, Sf, Ks, Ss;
        mv8x2(wk, wsn, hAf, fk, fs);
        red84(fk, fs, Kf, Sf);
        mv8x2(wk, wsn, hAs, fk, fs);
        red84(fk, fs, Ks, Ss);
        Kf += __shfl_xor_sync(0xffffffffu, Sf, 2);
        Ks += __shfl_xor_sync(0xffffffffu, Ss, 2);
        Kf += __shfl_xor_sync(0xffffffffu, Ks, 1);
        const float t = tanha(Kf + pA_bias);       // valid on q2/q3 (bias = bacc)
        accq = 0.9f * accq + 0.1f * t * ewpq;
    }

    // ---- epilogue: out[b] = (h_f + acc_f) . W_out + b_out
    if (q & 2) hatts[p][hoff] = accq;   // q2 -> acc[b0], q3 -> acc[b1]
    __syncthreads();
    const int w = tid >> 5, l = tid & 31;
    if (w < NB) {
        float pacc = 0.0f;
#pragma unroll
        for (int i = 0; i < HH / 32; i++) {
            const int jo = i * PAD + l;
            pacc += (hs[w][jo] + hatts[w][jo]) * W_out[l + 32 * i];
        }
#pragma unroll
        for (int o = 16; o; o >>= 1) pacc += __shfl_xor_sync(0xffffffffu, pacc, o);
        if (l == 0) out[b0 + w] = pacc + b_out[0];
    }
}

extern "C" void kernel_launch(void* const* d_in, const int* in_sizes, int n_in,
                              void* d_out, int out_size) {
    const float* x     = (const float*)d_in[0];
    const float* W_in  = (const float*)d_in[1];
    const float* b_in  = (const float*)d_in[2];
    const float* W_rec = (const float*)d_in[3];
    const float* b_rec = (const float*)d_in[4];
    const float* tau   = (const float*)d_in[5];
    const float* W_att = (const float*)d_in[6];
    const float* b_att = (const float*)d_in[7];
    const float* W_ev  = (const float*)d_in[8];
    const float* b_ev  = (const float*)d_in[9];
    const float* W_acc = (const float*)d_in[10];
    const float* b_acc = (const float*)d_in[11];
    const float* W_out = (const float*)d_in[12];
    const float* b_out = (const float*)d_in[13];
    float* out = (float*)d_out;

    liquid_scan_kernel<<<BB / NB, NTHREADS>>>(x, W_in, b_in, W_rec, b_rec, tau,
                                              W_att, b_att, W_ev, b_ev,
                                              W_acc, b_acc, W_out, b_out, out);
}